// round 6
// baseline (speedup 1.0000x reference)
#include <cuda_runtime.h>
#include <cuda_bf16.h>

// Problem constants
#define NUM_CW   512
#define CDIM     64
#define CHUNK_K  128            // codewords resident in smem per chunk
#define N_CHUNKS (NUM_CW / CHUNK_K)
#define N_IMG    32
#define HWSZ     4096           // 64*64
#define T_TOK    (N_IMG * HWSZ) // 131072 tokens
#define GAMMA_F  0.99f
#define TN       4              // codewords per inner group (indep. acc chains)
#define TM       2              // tokens per thread

// Output layout: q | codebook_new | N_new | m_new
#define OFF_Q   0
#define OFF_CB  (N_IMG * CDIM * HWSZ)          // 8388608
#define OFF_N   (OFF_CB + NUM_CW * CDIM)       // 8421376
#define OFF_M   (OFF_N + NUM_CW)               // 8421888

// Scratch (device globals; zeroed at load, re-zeroed by finalize each call)
__device__ float g_counts[NUM_CW];
__device__ float g_sums[NUM_CW * CDIM];
__device__ float g_cnorm[NUM_CW];

#define FMA_F32X2(acc, a, b) \
    asm("fma.rn.f32x2 %0, %1, %2, %0;" : "+l"(acc) : "l"(a), "l"(b))
#define PACK2(out, lo, hi) \
    asm("mov.b64 %0, {%1, %2};" : "=l"(out) : "f"(lo), "f"(hi))
#define UNPACK2(lo, hi, in) \
    asm("mov.b64 {%0, %1}, %2;" : "=f"(lo), "=f"(hi) : "l"(in))

// Coalesced norm computation: thread i squares codebook[i]; warp-shuffle
// reduces each 32-lane half-row; lane 0 atomically combines into g_cnorm.
__global__ void init_kernel(const float* __restrict__ codebook) {
    int i = blockIdx.x * blockDim.x + threadIdx.x;  // 0 .. 32767
    float v = codebook[i];
    float s = v * v;
#pragma unroll
    for (int off = 16; off > 0; off >>= 1)
        s += __shfl_down_sync(0xFFFFFFFFu, s, off);
    if ((threadIdx.x & 31) == 0)
        atomicAdd(&g_cnorm[i >> 6], s);
}

// Each thread owns TM=2 tokens (tid and tid+128 within a 256-token block),
// so each broadcast LDS.128 of codeword data feeds 2x the FFMA2 work.
__global__ __launch_bounds__(128, 2)
void assign_kernel(const float* __restrict__ x,
                   const float* __restrict__ codebook,
                   float* __restrict__ out) {
    __shared__ float scb[CHUNK_K * CDIM];   // 32 KB
    __shared__ float snorm[CHUNK_K];

    const int tid = threadIdx.x;
    const int t0  = blockIdx.x * 256 + tid;      // token A
    const int t1  = t0 + 128;                    // token B (same image n)
    const int n   = t0 >> 12;
    const int hw0 = t0 & (HWSZ - 1);
    const int hw1 = t1 & (HWSZ - 1);
    const int base0 = n * (CDIM * HWSZ) + hw0;
    const int base1 = n * (CDIM * HWSZ) + hw1;

    // x features for both tokens, packed as f32x2 (channels 2i, 2i+1)
    unsigned long long xa[CDIM / 2], xb[CDIM / 2];
#pragma unroll
    for (int i = 0; i < CDIM / 2; i++) {
        float a0 = x[base0 + (2 * i) * HWSZ];
        float a1 = x[base0 + (2 * i + 1) * HWSZ];
        PACK2(xa[i], a0, a1);
        float b0 = x[base1 + (2 * i) * HWSZ];
        float b1 = x[base1 + (2 * i + 1) * HWSZ];
        PACK2(xb[i], b0, b1);
    }

    float best_da = 3.4e38f, best_db = 3.4e38f;
    int   best_ka = 0,       best_kb = 0;

    for (int ch = 0; ch < N_CHUNKS; ch++) {
        __syncthreads();
        {
            const float4* src = (const float4*)(codebook + ch * CHUNK_K * CDIM);
            float4* dst = (float4*)scb;
#pragma unroll
            for (int i = 0; i < (CHUNK_K * CDIM / 4) / 128; i++)
                dst[tid + i * 128] = src[tid + i * 128];
            snorm[tid] = g_cnorm[ch * CHUNK_K + tid];
        }
        __syncthreads();

        const ulonglong2* cb2 = (const ulonglong2*)scb;  // 16 per codeword row
#pragma unroll 1
        for (int g = 0; g < CHUNK_K / TN; g++) {
            unsigned long long acca[TN], accb[TN];
#pragma unroll
            for (int j = 0; j < TN; j++) { acca[j] = 0ULL; accb[j] = 0ULL; }

            const ulonglong2* r0 = cb2 + (g * TN) * (CDIM / 4);
#pragma unroll
            for (int i = 0; i < CDIM / 4; i++) {
#pragma unroll
                for (int j = 0; j < TN; j++) {
                    ulonglong2 v = r0[j * (CDIM / 4) + i];  // broadcast LDS.128
                    FMA_F32X2(acca[j], xa[2 * i],     v.x);
                    FMA_F32X2(acca[j], xa[2 * i + 1], v.y);
                    FMA_F32X2(accb[j], xb[2 * i],     v.x);
                    FMA_F32X2(accb[j], xb[2 * i + 1], v.y);
                }
            }
#pragma unroll
            for (int j = 0; j < TN; j++) {
                int k = ch * CHUNK_K + g * TN + j;
                float nrm = snorm[g * TN + j];
                float lo, hi;
                UNPACK2(lo, hi, acca[j]);
                float da = fmaf(-2.0f, lo + hi, nrm);
                if (da < best_da) { best_da = da; best_ka = k; }
                UNPACK2(lo, hi, accb[j]);
                float db = fmaf(-2.0f, lo + hi, nrm);
                if (db < best_db) { best_db = db; best_kb = k; }
            }
        }
    }

    // Write q for both tokens (strided layout, coalesced across the warp)
    const float4* cwa = (const float4*)(codebook + best_ka * CDIM);
    const float4* cwb = (const float4*)(codebook + best_kb * CDIM);
#pragma unroll
    for (int i = 0; i < CDIM / 4; i++) {
        float4 va = cwa[i];
        out[OFF_Q + base0 + (4 * i + 0) * HWSZ] = va.x;
        out[OFF_Q + base0 + (4 * i + 1) * HWSZ] = va.y;
        out[OFF_Q + base0 + (4 * i + 2) * HWSZ] = va.z;
        out[OFF_Q + base0 + (4 * i + 3) * HWSZ] = va.w;
        float4 vb = cwb[i];
        out[OFF_Q + base1 + (4 * i + 0) * HWSZ] = vb.x;
        out[OFF_Q + base1 + (4 * i + 1) * HWSZ] = vb.y;
        out[OFF_Q + base1 + (4 * i + 2) * HWSZ] = vb.z;
        out[OFF_Q + base1 + (4 * i + 3) * HWSZ] = vb.w;
    }

    // EMA stats
    atomicAdd(&g_counts[best_ka], 1.0f);
    atomicAdd(&g_counts[best_kb], 1.0f);
    float* sa = &g_sums[best_ka * CDIM];
    float* sb = &g_sums[best_kb * CDIM];
#pragma unroll
    for (int i = 0; i < CDIM / 2; i++) {
        float u, v;
        UNPACK2(u, v, xa[i]);
        atomicAdd(&sa[2 * i],     u);
        atomicAdd(&sa[2 * i + 1], v);
        UNPACK2(u, v, xb[i]);
        atomicAdd(&sb[2 * i],     u);
        atomicAdd(&sb[2 * i + 1], v);
    }
}

// One thread per (k, c). Also resets scratch for the next call.
__global__ void finalize_kernel(const float* __restrict__ N_state,
                                const float* __restrict__ m_state,
                                float* __restrict__ out) {
    int i = blockIdx.x * blockDim.x + threadIdx.x;
    if (i >= NUM_CW * CDIM) return;
    int k = i / CDIM;
    float cnt = g_counts[k];
    bool occ = cnt > 0.0f;
    float Nold = N_state[k];
    float Nn = occ ? (Nold * GAMMA_F + cnt * (1.0f - GAMMA_F)) : Nold;
    float mold = m_state[i];
    float mn = occ ? (mold * GAMMA_F + g_sums[i] * (1.0f - GAMMA_F)) : mold;
    out[OFF_M + i]  = mn;
    out[OFF_CB + i] = mn / Nn;
    g_sums[i] = 0.0f;
    if ((i % CDIM) == 0) out[OFF_N + k] = Nn;
    if (i < NUM_CW) { g_counts[i] = 0.0f; g_cnorm[i] = 0.0f; }
}

extern "C" void kernel_launch(void* const* d_in, const int* in_sizes, int n_in,
                              void* d_out, int out_size) {
    const float* x        = (const float*)d_in[0];
    const float* codebook = (const float*)d_in[1];
    const float* N_state  = (const float*)d_in[2];
    const float* m_state  = (const float*)d_in[3];
    float* out = (float*)d_out;

    init_kernel<<<NUM_CW * CDIM / 256, 256>>>(codebook);
    assign_kernel<<<T_TOK / 256, 128>>>(x, codebook, out);
    finalize_kernel<<<(NUM_CW * CDIM + 255) / 256, 256>>>(N_state, m_state, out);
}

// round 7
// speedup vs baseline: 1.0025x; 1.0025x over previous
#include <cuda_runtime.h>
#include <cuda_bf16.h>

// Problem constants
#define NUM_CW   512
#define CDIM     64
#define CHUNK_K  128            // codewords resident in smem per chunk
#define N_CHUNKS (NUM_CW / CHUNK_K)
#define N_IMG    32
#define HWSZ     4096           // 64*64
#define T_TOK    (N_IMG * HWSZ) // 131072 tokens
#define GAMMA_F  0.99f
#define TN       4              // codewords per inner group (indep. acc chains)
#define TM       2              // tokens per thread

// Output layout: q | codebook_new | N_new | m_new
#define OFF_Q   0
#define OFF_CB  (N_IMG * CDIM * HWSZ)          // 8388608
#define OFF_N   (OFF_CB + NUM_CW * CDIM)       // 8421376
#define OFF_M   (OFF_N + NUM_CW)               // 8421888

// Scratch (device globals; zeroed at load, re-zeroed by finalize each call)
__device__ float g_counts[NUM_CW];
__device__ float g_sums[NUM_CW * CDIM];
__device__ float g_cnorm[NUM_CW];

#define FMA_F32X2(acc, a, b) \
    asm("fma.rn.f32x2 %0, %1, %2, %0;" : "+l"(acc) : "l"(a), "l"(b))
#define PACK2(out, lo, hi) \
    asm("mov.b64 %0, {%1, %2};" : "=l"(out) : "f"(lo), "f"(hi))
#define UNPACK2(lo, hi, in) \
    asm("mov.b64 {%0, %1}, %2;" : "=f"(lo), "=f"(hi) : "l"(in))

// Coalesced norm computation: thread i squares codebook[i]; warp-shuffle
// reduces each 32-lane half-row; lane 0 atomically combines into g_cnorm.
__global__ void init_kernel(const float* __restrict__ codebook) {
    int i = blockIdx.x * blockDim.x + threadIdx.x;  // 0 .. 32767
    float v = codebook[i];
    float s = v * v;
#pragma unroll
    for (int off = 16; off > 0; off >>= 1)
        s += __shfl_down_sync(0xFFFFFFFFu, s, off);
    if ((threadIdx.x & 31) == 0)
        atomicAdd(&g_cnorm[i >> 6], s);
}

// Each thread owns TM=2 tokens (tid and tid+128 within a 256-token block),
// so each broadcast LDS.128 of codeword data feeds 2x the FFMA2 work.
__global__ __launch_bounds__(128, 2)
void assign_kernel(const float* __restrict__ x,
                   const float* __restrict__ codebook,
                   float* __restrict__ out) {
    __shared__ float scb[CHUNK_K * CDIM];   // 32 KB
    __shared__ float snorm[CHUNK_K];

    const int tid = threadIdx.x;
    const int t0  = blockIdx.x * 256 + tid;      // token A
    const int t1  = t0 + 128;                    // token B (same image n)
    const int n   = t0 >> 12;
    const int hw0 = t0 & (HWSZ - 1);
    const int hw1 = t1 & (HWSZ - 1);
    const int base0 = n * (CDIM * HWSZ) + hw0;
    const int base1 = n * (CDIM * HWSZ) + hw1;

    // x features for both tokens, packed as f32x2 (channels 2i, 2i+1)
    unsigned long long xa[CDIM / 2], xb[CDIM / 2];
#pragma unroll
    for (int i = 0; i < CDIM / 2; i++) {
        float a0 = x[base0 + (2 * i) * HWSZ];
        float a1 = x[base0 + (2 * i + 1) * HWSZ];
        PACK2(xa[i], a0, a1);
        float b0 = x[base1 + (2 * i) * HWSZ];
        float b1 = x[base1 + (2 * i + 1) * HWSZ];
        PACK2(xb[i], b0, b1);
    }

    float best_da = 3.4e38f, best_db = 3.4e38f;
    int   best_ka = 0,       best_kb = 0;

    for (int ch = 0; ch < N_CHUNKS; ch++) {
        __syncthreads();
        {
            const float4* src = (const float4*)(codebook + ch * CHUNK_K * CDIM);
            float4* dst = (float4*)scb;
#pragma unroll
            for (int i = 0; i < (CHUNK_K * CDIM / 4) / 128; i++)
                dst[tid + i * 128] = src[tid + i * 128];
            snorm[tid] = g_cnorm[ch * CHUNK_K + tid];
        }
        __syncthreads();

        const ulonglong2* cb2 = (const ulonglong2*)scb;  // 16 per codeword row
#pragma unroll 1
        for (int g = 0; g < CHUNK_K / TN; g++) {
            unsigned long long acca[TN], accb[TN];
#pragma unroll
            for (int j = 0; j < TN; j++) { acca[j] = 0ULL; accb[j] = 0ULL; }

            const ulonglong2* r0 = cb2 + (g * TN) * (CDIM / 4);
#pragma unroll
            for (int i = 0; i < CDIM / 4; i++) {
#pragma unroll
                for (int j = 0; j < TN; j++) {
                    ulonglong2 v = r0[j * (CDIM / 4) + i];  // broadcast LDS.128
                    FMA_F32X2(acca[j], xa[2 * i],     v.x);
                    FMA_F32X2(acca[j], xa[2 * i + 1], v.y);
                    FMA_F32X2(accb[j], xb[2 * i],     v.x);
                    FMA_F32X2(accb[j], xb[2 * i + 1], v.y);
                }
            }
#pragma unroll
            for (int j = 0; j < TN; j++) {
                int k = ch * CHUNK_K + g * TN + j;
                float nrm = snorm[g * TN + j];
                float lo, hi;
                UNPACK2(lo, hi, acca[j]);
                float da = fmaf(-2.0f, lo + hi, nrm);
                if (da < best_da) { best_da = da; best_ka = k; }
                UNPACK2(lo, hi, accb[j]);
                float db = fmaf(-2.0f, lo + hi, nrm);
                if (db < best_db) { best_db = db; best_kb = k; }
            }
        }
    }

    // Write q for both tokens (strided layout, coalesced across the warp)
    const float4* cwa = (const float4*)(codebook + best_ka * CDIM);
    const float4* cwb = (const float4*)(codebook + best_kb * CDIM);
#pragma unroll
    for (int i = 0; i < CDIM / 4; i++) {
        float4 va = cwa[i];
        out[OFF_Q + base0 + (4 * i + 0) * HWSZ] = va.x;
        out[OFF_Q + base0 + (4 * i + 1) * HWSZ] = va.y;
        out[OFF_Q + base0 + (4 * i + 2) * HWSZ] = va.z;
        out[OFF_Q + base0 + (4 * i + 3) * HWSZ] = va.w;
        float4 vb = cwb[i];
        out[OFF_Q + base1 + (4 * i + 0) * HWSZ] = vb.x;
        out[OFF_Q + base1 + (4 * i + 1) * HWSZ] = vb.y;
        out[OFF_Q + base1 + (4 * i + 2) * HWSZ] = vb.z;
        out[OFF_Q + base1 + (4 * i + 3) * HWSZ] = vb.w;
    }

    // EMA stats
    atomicAdd(&g_counts[best_ka], 1.0f);
    atomicAdd(&g_counts[best_kb], 1.0f);
    float* sa = &g_sums[best_ka * CDIM];
    float* sb = &g_sums[best_kb * CDIM];
#pragma unroll
    for (int i = 0; i < CDIM / 2; i++) {
        float u, v;
        UNPACK2(u, v, xa[i]);
        atomicAdd(&sa[2 * i],     u);
        atomicAdd(&sa[2 * i + 1], v);
        UNPACK2(u, v, xb[i]);
        atomicAdd(&sb[2 * i],     u);
        atomicAdd(&sb[2 * i + 1], v);
    }
}

// One thread per (k, c). Also resets scratch for the next call.
__global__ void finalize_kernel(const float* __restrict__ N_state,
                                const float* __restrict__ m_state,
                                float* __restrict__ out) {
    int i = blockIdx.x * blockDim.x + threadIdx.x;
    if (i >= NUM_CW * CDIM) return;
    int k = i / CDIM;
    float cnt = g_counts[k];
    bool occ = cnt > 0.0f;
    float Nold = N_state[k];
    float Nn = occ ? (Nold * GAMMA_F + cnt * (1.0f - GAMMA_F)) : Nold;
    float mold = m_state[i];
    float mn = occ ? (mold * GAMMA_F + g_sums[i] * (1.0f - GAMMA_F)) : mold;
    out[OFF_M + i]  = mn;
    out[OFF_CB + i] = mn / Nn;
    g_sums[i] = 0.0f;
    if ((i % CDIM) == 0) out[OFF_N + k] = Nn;
    if (i < NUM_CW) { g_counts[i] = 0.0f; g_cnorm[i] = 0.0f; }
}

extern "C" void kernel_launch(void* const* d_in, const int* in_sizes, int n_in,
                              void* d_out, int out_size) {
    const float* x        = (const float*)d_in[0];
    const float* codebook = (const float*)d_in[1];
    const float* N_state  = (const float*)d_in[2];
    const float* m_state  = (const float*)d_in[3];
    float* out = (float*)d_out;

    init_kernel<<<NUM_CW * CDIM / 256, 256>>>(codebook);
    assign_kernel<<<T_TOK / 256, 128>>>(x, codebook, out);
    finalize_kernel<<<(NUM_CW * CDIM + 255) / 256, 256>>>(N_state, m_state, out);
}